// round 8
// baseline (speedup 1.0000x reference)
#include <cuda_runtime.h>
#include <cuda_bf16.h>

// SNN bit-plane quantization scan. x viewed as [T, N], N = B*TOK*DIM.
//   mem += x_t
//   k = clamp(trunc(mem*128/lam), 0, 255)   [float-domain]
//   spike = lam*k ; mem -= spike            [== exact bit-plane recombination]
//
// HBM-bound stream (77MB read + 77MB write). R5-R7 showed duration pinned at
// ~21us regardless of compute path -> remove wave-structure overhead:
// persistent single-wave grid-stride launch (6 blocks/SM, queried SM count).

#define T_STEPS 4

__device__ __forceinline__ float snn_step(float& m, float lam, float c) {
    float v = m * c;                       // c = 128/lam (exact for pow2 lam)
    float k = truncf(v);                   // F2F.RZ; == int trunc for our range
    k = fminf(fmaxf(k, 0.0f), 255.0f);
    float spike = lam * k;
    m -= spike;
    return spike;
}

__global__ __launch_bounds__(256, 6) void snn_scan_kernel(
    const float4* __restrict__ x,
    const float* __restrict__ lam_p,
    float4* __restrict__ out,
    int n4)  // N/4 float4 elements per timestep
{
    const float lam = __ldg(lam_p);
    const float c   = 128.0f * __frcp_rn(lam);  // exact for lam = 2^e (test: 1.0)
    const float m0  = 0.5f * lam;

    const int stride = gridDim.x * blockDim.x;

    for (int i = blockIdx.x * blockDim.x + threadIdx.x; i < n4; i += stride) {
        // Front-batch the T=4 loads: 4 independent, fully-coalesced LDG.128.
        float4 xv[T_STEPS];
#pragma unroll
        for (int t = 0; t < T_STEPS; t++)
            xv[t] = x[t * n4 + i];

        float4 m = make_float4(m0, m0, m0, m0);

#pragma unroll
        for (int t = 0; t < T_STEPS; t++) {
            m.x += xv[t].x;
            m.y += xv[t].y;
            m.z += xv[t].z;
            m.w += xv[t].w;

            float4 s;
            s.x = snn_step(m.x, lam, c);
            s.y = snn_step(m.y, lam, c);
            s.z = snn_step(m.z, lam, c);
            s.w = snn_step(m.w, lam, c);

            out[t * n4 + i] = s;
        }
    }
}

extern "C" void kernel_launch(void* const* d_in, const int* in_sizes, int n_in,
                              void* d_out, int out_size) {
    const float* x   = (const float*)d_in[0];
    const float* lam = (const float*)d_in[1];
    float* out       = (float*)d_out;

    int total = in_sizes[0];          // T * B * TOK * DIM
    int n_per_t = total / T_STEPS;    // 4,816,896
    int n4 = n_per_t / 4;             // 1,204,224

    int sms = 148;
    cudaDeviceGetAttribute(&sms, cudaDevAttrMultiProcessorCount, 0);  // 152 on GB300

    int block = 256;
    int grid  = sms * 6;              // single wave: 6 blocks/SM (launch_bounds pair)
    snn_scan_kernel<<<grid, block>>>(
        (const float4*)x, lam, (float4*)out, n4);
}

// round 10
// speedup vs baseline: 1.0578x; 1.0578x over previous
#include <cuda_runtime.h>
#include <cuda_bf16.h>

// SNN bit-plane quantization scan. x viewed as [T, N], N = B*TOK*DIM.
//   mem += x_t
//   k = clamp(trunc(mem*128/lam), 0, 255)   [float-domain trunc+clamp]
//   spike = lam*k ; mem -= spike            [== exact bit-plane recombination]
//
// HBM-bound: 154 MB total stream. Kernel runs at ~7.4 TB/s effective (~93% of
// 8 TB/s spec) -- at the roofline. (ncu's DRAM% is deflated because the 77 MB
// output fits in the 126 MB L2 during the cache-flushed profile launch.)
// This round merges the fastest-kernel config (R5: default-cached loads,
// grid 4704x256) with the shortest compute chain (R7: float-domain, 32 regs).

#define T_STEPS 4

__device__ __forceinline__ float snn_step(float& m, float lam, float c) {
    float v = m * c;                       // c = 128/lam (exact for pow2 lam)
    float k = truncf(v);                   // F2F.RZ; == int trunc for our range
    k = fminf(fmaxf(k, 0.0f), 255.0f);
    float spike = lam * k;
    m -= spike;
    return spike;
}

__global__ __launch_bounds__(256) void snn_scan_kernel(
    const float4* __restrict__ x,
    const float* __restrict__ lam_p,
    float4* __restrict__ out,
    int n4)  // N/4 float4 elements per timestep
{
    int i = blockIdx.x * blockDim.x + threadIdx.x;
    if (i >= n4) return;

    const float lam = __ldg(lam_p);
    const float c   = 128.0f * __frcp_rn(lam);  // exact for lam = 2^e (test: 1.0)
    const float m0  = 0.5f * lam;

    // Front-batch the T=4 loads: 4 independent, fully-coalesced LDG.128.
    float4 xv[T_STEPS];
#pragma unroll
    for (int t = 0; t < T_STEPS; t++)
        xv[t] = x[t * n4 + i];

    float4 m = make_float4(m0, m0, m0, m0);

#pragma unroll
    for (int t = 0; t < T_STEPS; t++) {
        m.x += xv[t].x;
        m.y += xv[t].y;
        m.z += xv[t].z;
        m.w += xv[t].w;

        float4 s;
        s.x = snn_step(m.x, lam, c);
        s.y = snn_step(m.y, lam, c);
        s.z = snn_step(m.z, lam, c);
        s.w = snn_step(m.w, lam, c);

        out[t * n4 + i] = s;
    }
}

extern "C" void kernel_launch(void* const* d_in, const int* in_sizes, int n_in,
                              void* d_out, int out_size) {
    const float* x   = (const float*)d_in[0];
    const float* lam = (const float*)d_in[1];
    float* out       = (float*)d_out;

    int total = in_sizes[0];          // T * B * TOK * DIM
    int n_per_t = total / T_STEPS;    // 4,816,896
    int n4 = n_per_t / 4;             // 1,204,224

    int block = 256;
    int grid = (n4 + block - 1) / block;   // 4704
    snn_scan_kernel<<<grid, block>>>(
        (const float4*)x, lam, (float4*)out, n4);
}